// round 1
// baseline (speedup 1.0000x reference)
#include <cuda_runtime.h>

#define N_NODES 100000
#define N_EDGES 3200000
#define IN_CH 32
#define HID 16

// ---------------- device scratch (no allocs allowed) ----------------
__device__ float g_p1[N_NODES][HID];    // x @ Wl1.T
__device__ float g_r1[N_NODES][HID];    // x @ Wr1.T
__device__ float g_agg1[N_NODES][HID];  // segsum(p1[src]) at dst
__device__ float g_deg[N_NODES];
__device__ float g_p2[N_NODES];         // h @ Wl2.T
__device__ float g_r2[N_NODES];         // h @ Wr2.T
__device__ float g_agg2[N_NODES];       // segsum(p2[src]) at dst
__device__ int   g_idx64;               // 1 if edge_index is int64, else int32

// ---------------- dtype detection for edge_index ----------------
// Indices are < 100000 < 2^17. If stored as little-endian int64, every odd
// 32-bit word is 0. Probability of false positive with int32 data over 256
// sampled words is ~(1e-5)^256 ~= 0.
__global__ void detect_kernel(const int* __restrict__ ei32) {
    __shared__ int s_or;
    if (threadIdx.x == 0) s_or = 0;
    __syncthreads();
    int v = ei32[2 * threadIdx.x + 1];
    if (v != 0) atomicOr(&s_or, 1);
    __syncthreads();
    if (threadIdx.x == 0) g_idx64 = (s_or == 0) ? 1 : 0;
}

// ---------------- zero accumulators (out is poisoned; globals persist) ----
__global__ void zero_kernel() {
    int i = blockIdx.x * blockDim.x + threadIdx.x;
    if (i < N_NODES * HID) (&g_agg1[0][0])[i] = 0.0f;
    if (i < N_NODES) { g_deg[i] = 0.0f; g_agg2[i] = 0.0f; }
}

// ---------------- projections p1 = x@Wl1.T, r1 = x@Wr1.T ----------------
__global__ void proj1_kernel(const float* __restrict__ x,
                             const float* __restrict__ Wl1,
                             const float* __restrict__ Wr1) {
    __shared__ float sWl[HID * IN_CH];
    __shared__ float sWr[HID * IN_CH];
    for (int t = threadIdx.x; t < HID * IN_CH; t += blockDim.x) {
        sWl[t] = Wl1[t];
        sWr[t] = Wr1[t];
    }
    __syncthreads();
    int i = blockIdx.x * blockDim.x + threadIdx.x;
    if (i >= N_NODES) return;

    float xr[IN_CH];
    const float4* xp = reinterpret_cast<const float4*>(x + (size_t)i * IN_CH);
#pragma unroll
    for (int j = 0; j < IN_CH / 4; j++) {
        float4 v = __ldg(&xp[j]);
        xr[4 * j + 0] = v.x; xr[4 * j + 1] = v.y;
        xr[4 * j + 2] = v.z; xr[4 * j + 3] = v.w;
    }
#pragma unroll
    for (int k = 0; k < HID; k++) {
        float pl = 0.0f, pr = 0.0f;
#pragma unroll
        for (int j = 0; j < IN_CH; j++) {
            pl = fmaf(xr[j], sWl[k * IN_CH + j], pl);
            pr = fmaf(xr[j], sWr[k * IN_CH + j], pr);
        }
        g_p1[i][k] = pl;
        g_r1[i][k] = pr;
    }
}

// ---------------- edge pass 1: deg count + scatter p1[src] -> agg1[dst] ---
__device__ __forceinline__ void load_edge(const void* ei, int e, int& s, int& d) {
    if (g_idx64) {
        const long long* p = (const long long*)ei;
        s = (int)__ldg(&p[e]);
        d = (int)__ldg(&p[N_EDGES + e]);
    } else {
        const int* p = (const int*)ei;
        s = __ldg(&p[e]);
        d = __ldg(&p[N_EDGES + e]);
    }
}

__global__ void edge1_kernel(const void* __restrict__ ei) {
    int e = blockIdx.x * blockDim.x + threadIdx.x;
    if (e >= N_EDGES) return;
    int s, d;
    load_edge(ei, e, s, d);

    asm volatile("red.global.add.f32 [%0], %1;"
                 :: "l"(&g_deg[d]), "f"(1.0f) : "memory");

    const float4* ps = reinterpret_cast<const float4*>(g_p1[s]);
    float4* pd = reinterpret_cast<float4*>(g_agg1[d]);
#pragma unroll
    for (int i = 0; i < HID / 4; i++) {
        float4 v = __ldg(&ps[i]);
        asm volatile("red.global.add.v4.f32 [%0], {%1, %2, %3, %4};"
                     :: "l"(pd + i), "f"(v.x), "f"(v.y), "f"(v.z), "f"(v.w)
                     : "memory");
    }
}

// ---------------- mid: h = relu(deg_inv*agg1 + b1 + r1); p2,r2 = h@W2 -----
__global__ void mid_kernel(const float* __restrict__ b1,
                           const float* __restrict__ Wl2,
                           const float* __restrict__ Wr2) {
    int i = blockIdx.x * blockDim.x + threadIdx.x;
    if (i >= N_NODES) return;
    float dinv = 1.0f / fmaxf(g_deg[i], 1.0f);
    float p2 = 0.0f, r2 = 0.0f;
#pragma unroll
    for (int k = 0; k < HID; k++) {
        float h = fmaf(g_agg1[i][k], dinv, __ldg(&b1[k]) + g_r1[i][k]);
        h = fmaxf(h, 0.0f);
        p2 = fmaf(h, __ldg(&Wl2[k]), p2);
        r2 = fmaf(h, __ldg(&Wr2[k]), r2);
    }
    g_p2[i] = p2;
    g_r2[i] = r2;
}

// ---------------- edge pass 2: scalar scatter p2[src] -> agg2[dst] --------
__global__ void edge2_kernel(const void* __restrict__ ei) {
    int e = blockIdx.x * blockDim.x + threadIdx.x;
    if (e >= N_EDGES) return;
    int s, d;
    load_edge(ei, e, s, d);
    float v = __ldg(&g_p2[s]);
    asm volatile("red.global.add.f32 [%0], %1;"
                 :: "l"(&g_agg2[d]), "f"(v) : "memory");
}

// ---------------- final: out = deg_inv*agg2 + b2 + r2 ----------------
__global__ void final_kernel(const float* __restrict__ b2,
                             float* __restrict__ out) {
    int i = blockIdx.x * blockDim.x + threadIdx.x;
    if (i >= N_NODES) return;
    float dinv = 1.0f / fmaxf(g_deg[i], 1.0f);
    out[i] = fmaf(g_agg2[i], dinv, __ldg(&b2[0]) + g_r2[i]);
}

// ---------------- launch ----------------
extern "C" void kernel_launch(void* const* d_in, const int* in_sizes, int n_in,
                              void* d_out, int out_size) {
    const float* x   = (const float*)d_in[0];
    const void*  ei  = d_in[1];
    const float* Wl1 = (const float*)d_in[2];
    const float* Wr1 = (const float*)d_in[3];
    const float* b1  = (const float*)d_in[4];
    const float* Wl2 = (const float*)d_in[5];
    const float* Wr2 = (const float*)d_in[6];
    const float* b2  = (const float*)d_in[7];
    float* out = (float*)d_out;

    const int T = 256;
    detect_kernel<<<1, 256>>>((const int*)ei);
    zero_kernel<<<(N_NODES * HID + T - 1) / T, T>>>();
    proj1_kernel<<<(N_NODES + T - 1) / T, T>>>(x, Wl1, Wr1);
    edge1_kernel<<<(N_EDGES + T - 1) / T, T>>>(ei);
    mid_kernel<<<(N_NODES + T - 1) / T, T>>>(b1, Wl2, Wr2);
    edge2_kernel<<<(N_EDGES + T - 1) / T, T>>>(ei);
    final_kernel<<<(N_NODES + T - 1) / T, T>>>(b2, out);
}

// round 2
// speedup vs baseline: 1.1891x; 1.1891x over previous
#include <cuda_runtime.h>

#define N_NODES 100000
#define N_EDGES 3200000
#define IN_CH 32
#define HID 16
#define SCAN_B 512
#define NB ((N_NODES + SCAN_B - 1) / SCAN_B)   // 196

// ---------------- device scratch (no allocs allowed) ----------------
__device__ float g_p1[N_NODES][HID];    // x @ Wl1.T
__device__ float g_r1[N_NODES][HID];    // x @ Wr1.T
__device__ float g_p2[N_NODES];         // h @ Wl2.T
__device__ float g_r2[N_NODES];         // h @ Wr2.T
__device__ int   g_cnt[N_NODES];        // in-degree histogram
__device__ int   g_rowptr[N_NODES + 1]; // CSR row pointers (by dst)
__device__ int   g_woff[N_NODES];       // scatter write cursors
__device__ int   g_bsum[NB];            // scan block sums
__device__ int   g_srcs[N_EDGES];       // src ids bucketed by dst
__device__ int   g_idx64;               // 1 if edge_index is int64

// ---------------- dtype detection for edge_index ----------------
__global__ void detect_kernel(const int* __restrict__ ei32) {
    __shared__ int s_or;
    if (threadIdx.x == 0) s_or = 0;
    __syncthreads();
    int v = ei32[2 * threadIdx.x + 1];
    if (v != 0) atomicOr(&s_or, 1);
    __syncthreads();
    if (threadIdx.x == 0) g_idx64 = (s_or == 0) ? 1 : 0;
}

__global__ void zero_kernel() {
    int i = blockIdx.x * blockDim.x + threadIdx.x;
    if (i < N_NODES) g_cnt[i] = 0;
}

// ---------------- edge loads ----------------
__device__ __forceinline__ void load_edge(const void* ei, int e, int& s, int& d) {
    if (g_idx64) {
        const long long* p = (const long long*)ei;
        s = (int)__ldg(&p[e]);
        d = (int)__ldg(&p[N_EDGES + e]);
    } else {
        const int* p = (const int*)ei;
        s = __ldg(&p[e]);
        d = __ldg(&p[N_EDGES + e]);
    }
}

__device__ __forceinline__ int load_dst(const void* ei, int e) {
    if (g_idx64) return (int)__ldg(&((const long long*)ei)[N_EDGES + e]);
    return __ldg(&((const int*)ei)[N_EDGES + e]);
}

// ---------------- CSR build: histogram -> scan -> scatter ----------------
__global__ void hist_kernel(const void* __restrict__ ei) {
    int e = blockIdx.x * blockDim.x + threadIdx.x;
    if (e >= N_EDGES) return;
    atomicAdd(&g_cnt[load_dst(ei, e)], 1);
}

__global__ void scanA_kernel() {
    __shared__ int s[SCAN_B];
    int t = blockIdx.x * SCAN_B + threadIdx.x;
    int v = (t < N_NODES) ? g_cnt[t] : 0;
    s[threadIdx.x] = v;
    __syncthreads();
    for (int off = 1; off < SCAN_B; off <<= 1) {
        int tv = (threadIdx.x >= off) ? s[threadIdx.x - off] : 0;
        __syncthreads();
        s[threadIdx.x] += tv;
        __syncthreads();
    }
    if (t < N_NODES) g_rowptr[t] = s[threadIdx.x] - v;  // exclusive
    if (threadIdx.x == SCAN_B - 1) g_bsum[blockIdx.x] = s[SCAN_B - 1];
}

__global__ void scanB_kernel() {
    __shared__ int s[256];
    int v = (threadIdx.x < NB) ? g_bsum[threadIdx.x] : 0;
    s[threadIdx.x] = v;
    __syncthreads();
    for (int off = 1; off < 256; off <<= 1) {
        int tv = (threadIdx.x >= off) ? s[threadIdx.x - off] : 0;
        __syncthreads();
        s[threadIdx.x] += tv;
        __syncthreads();
    }
    if (threadIdx.x < NB) g_bsum[threadIdx.x] = s[threadIdx.x] - v;  // exclusive
}

__global__ void scanC_kernel() {
    int t = blockIdx.x * blockDim.x + threadIdx.x;
    if (t < N_NODES) {
        int r = g_rowptr[t] + g_bsum[t / SCAN_B];
        g_rowptr[t] = r;
        g_woff[t] = r;
    }
    if (t == 0) g_rowptr[N_NODES] = N_EDGES;
}

__global__ void scatter_kernel(const void* __restrict__ ei) {
    int e = blockIdx.x * blockDim.x + threadIdx.x;
    if (e >= N_EDGES) return;
    int s, d;
    load_edge(ei, e, s, d);
    int pos = atomicAdd(&g_woff[d], 1);
    g_srcs[pos] = s;
}

// ---------------- projections p1 = x@Wl1.T, r1 = x@Wr1.T ----------------
__global__ void proj1_kernel(const float* __restrict__ x,
                             const float* __restrict__ Wl1,
                             const float* __restrict__ Wr1) {
    __shared__ float sWl[HID * IN_CH];
    __shared__ float sWr[HID * IN_CH];
    for (int t = threadIdx.x; t < HID * IN_CH; t += blockDim.x) {
        sWl[t] = Wl1[t];
        sWr[t] = Wr1[t];
    }
    __syncthreads();
    int i = blockIdx.x * blockDim.x + threadIdx.x;
    if (i >= N_NODES) return;

    float xr[IN_CH];
    const float4* xp = reinterpret_cast<const float4*>(x + (size_t)i * IN_CH);
#pragma unroll
    for (int j = 0; j < IN_CH / 4; j++) {
        float4 v = __ldg(&xp[j]);
        xr[4 * j + 0] = v.x; xr[4 * j + 1] = v.y;
        xr[4 * j + 2] = v.z; xr[4 * j + 3] = v.w;
    }
#pragma unroll
    for (int k = 0; k < HID; k++) {
        float pl = 0.0f, pr = 0.0f;
#pragma unroll
        for (int j = 0; j < IN_CH; j++) {
            pl = fmaf(xr[j], sWl[k * IN_CH + j], pl);
            pr = fmaf(xr[j], sWr[k * IN_CH + j], pr);
        }
        g_p1[i][k] = pl;
        g_r1[i][k] = pr;
    }
}

// ---------------- gather layer 1 (fused relu + layer-2 projections) ------
// One warp per node. Lanes 0-15 handle even edges, 16-31 odd edges; each
// lane owns channel (lane & 15). 16-lane loads of p1[src][0..15] = 64B
// coalesced. After edge loop: fold halves, relu, project to p2/r2 via
// half-warp shuffle reduce.
__global__ void gather1_kernel(const float* __restrict__ b1,
                               const float* __restrict__ Wl2,
                               const float* __restrict__ Wr2) {
    int warp = (blockIdx.x * blockDim.x + threadIdx.x) >> 5;
    int lane = threadIdx.x & 31;
    if (warp >= N_NODES) return;
    int node = warp;
    int start = g_rowptr[node];
    int end = g_rowptr[node + 1];
    int ch = lane & 15;
    int half = lane >> 4;

    float acc = 0.0f;
    for (int e = start + half; e < end; e += 2) {
        int s = __ldg(&g_srcs[e]);
        acc += g_p1[s][ch];
    }
    acc += __shfl_down_sync(0xffffffffu, acc, 16);  // lanes 0-15: full sum

    float dinv = 1.0f / fmaxf((float)(end - start), 1.0f);
    float h = fmaf(acc, dinv, __ldg(&b1[ch]) + g_r1[node][ch]);
    h = fmaxf(h, 0.0f);
    float p2 = h * __ldg(&Wl2[ch]);
    float r2 = h * __ldg(&Wr2[ch]);
#pragma unroll
    for (int o = 8; o; o >>= 1) {
        p2 += __shfl_down_sync(0xffffffffu, p2, o);
        r2 += __shfl_down_sync(0xffffffffu, r2, o);
    }
    if (lane == 0) {
        g_p2[node] = p2;
        g_r2[node] = r2;
    }
}

// ---------------- gather layer 2 (fused final epilogue) ----------------
__global__ void gather2_kernel(const float* __restrict__ b2,
                               float* __restrict__ out) {
    int warp = (blockIdx.x * blockDim.x + threadIdx.x) >> 5;
    int lane = threadIdx.x & 31;
    if (warp >= N_NODES) return;
    int start = g_rowptr[warp];
    int end = g_rowptr[warp + 1];
    float acc = 0.0f;
    for (int e = start + lane; e < end; e += 32)
        acc += __ldg(&g_p2[__ldg(&g_srcs[e])]);
#pragma unroll
    for (int o = 16; o; o >>= 1)
        acc += __shfl_down_sync(0xffffffffu, acc, o);
    if (lane == 0) {
        float dinv = 1.0f / fmaxf((float)(end - start), 1.0f);
        out[warp] = fmaf(acc, dinv, __ldg(&b2[0]) + g_r2[warp]);
    }
}

// ---------------- launch ----------------
extern "C" void kernel_launch(void* const* d_in, const int* in_sizes, int n_in,
                              void* d_out, int out_size) {
    const float* x   = (const float*)d_in[0];
    const void*  ei  = d_in[1];
    const float* Wl1 = (const float*)d_in[2];
    const float* Wr1 = (const float*)d_in[3];
    const float* b1  = (const float*)d_in[4];
    const float* Wl2 = (const float*)d_in[5];
    const float* Wr2 = (const float*)d_in[6];
    const float* b2  = (const float*)d_in[7];
    float* out = (float*)d_out;

    const int T = 256;
    const int EG = (N_EDGES + T - 1) / T;          // 12500
    const int NG = (N_NODES + T - 1) / T;          // 391
    const int WG = (N_NODES * 32 + T - 1) / T;     // 12500 (warp per node)

    detect_kernel<<<1, 256>>>((const int*)ei);
    zero_kernel<<<NG, T>>>();
    hist_kernel<<<EG, T>>>(ei);
    scanA_kernel<<<NB, SCAN_B>>>();
    scanB_kernel<<<1, 256>>>();
    scanC_kernel<<<NG, T>>>();
    scatter_kernel<<<EG, T>>>(ei);
    proj1_kernel<<<NG, T>>>(x, Wl1, Wr1);
    gather1_kernel<<<WG, T>>>(b1, Wl2, Wr2);
    gather2_kernel<<<WG, T>>>(b2, out);
}